// round 1
// baseline (speedup 1.0000x reference)
#include <cuda_runtime.h>

// Problem constants
#define Gn    128
#define NPGn  512
#define Hn    128
#define Vn    64
#define EPGn  8192
#define Nn    (Gn * NPGn)      // 65536
#define En    (Gn * EPGn)      // 1048576
#define OUTn  10

// ---------------- scratch (device globals; no allocation allowed) -----------
__device__ float g_Wf[Hn * Hn];
__device__ float g_bf[Hn];
__device__ float g_h1[(size_t)Nn * Hn];      // 32 MB
__device__ float g_h2[(size_t)Nn * Hn];      // 32 MB
__device__ float g_virt[(size_t)Gn * Vn * Hn];   // 4 MB
__device__ float g_virt2[(size_t)Gn * Vn * Hn];  // 4 MB
__device__ float g_m2[Gn * Hn];
__device__ float g_gf[Gn * Hn];
__device__ float g_f1[Gn * Hn];

// ---------------- tiny generic GEMM: one thread per output ------------------
__global__ void small_gemm(const float* __restrict__ A, const float* __restrict__ B,
                           const float* __restrict__ bias, float* __restrict__ C,
                           int M, int N, int K, int relu)
{
    int idx = blockIdx.x * blockDim.x + threadIdx.x;
    if (idx >= M * N) return;
    int m = idx / N, n = idx - m * N;
    float acc = bias ? bias[n] : 0.0f;
    for (int k = 0; k < K; k++)
        acc = fmaf(A[(size_t)m * K + k], B[(size_t)k * N + n], acc);
    if (relu) acc = fmaxf(acc, 0.0f);
    C[idx] = acc;
}

// ---------------- SGEMM: C[M,128] = A[M,128] @ B[128,128] + bias (opt relu) -
// Block tile 128x128, BK=8, 256 threads, 8x8 register tiles.
__global__ __launch_bounds__(256) void sgemm128(
    const float* __restrict__ A, const float* __restrict__ B,
    const float* __restrict__ bias, float* __restrict__ C, int relu)
{
    __shared__ float As[8][128];   // transposed A tile
    __shared__ float Bs[8][128];
    int tid  = threadIdx.x;
    int row0 = blockIdx.x * 128;
    int tr = tid >> 4;             // 0..15 -> rows tr*8..tr*8+7
    int tc = tid & 15;             // 0..15 -> cols tc*8..tc*8+7
    int aRow = tid >> 1, aCol = (tid & 1) * 4;
    int bRow = tid >> 5, bCol = (tid & 31) * 4;

    float acc[8][8];
#pragma unroll
    for (int i = 0; i < 8; i++)
#pragma unroll
        for (int j = 0; j < 8; j++) acc[i][j] = 0.0f;

    for (int k0 = 0; k0 < 128; k0 += 8) {
        float4 av = *(const float4*)(A + (size_t)(row0 + aRow) * 128 + k0 + aCol);
        float4 bv = *(const float4*)(B + (size_t)(k0 + bRow) * 128 + bCol);
        __syncthreads();
        As[aCol + 0][aRow] = av.x;
        As[aCol + 1][aRow] = av.y;
        As[aCol + 2][aRow] = av.z;
        As[aCol + 3][aRow] = av.w;
        *(float4*)&Bs[bRow][bCol] = bv;
        __syncthreads();
#pragma unroll
        for (int kk = 0; kk < 8; kk++) {
            float am[8], bn[8];
#pragma unroll
            for (int i = 0; i < 8; i++) am[i] = As[kk][tr * 8 + i];
#pragma unroll
            for (int j = 0; j < 8; j++) bn[j] = Bs[kk][tc * 8 + j];
#pragma unroll
            for (int i = 0; i < 8; i++)
#pragma unroll
                for (int j = 0; j < 8; j++)
                    acc[i][j] = fmaf(am[i], bn[j], acc[i][j]);
        }
    }

#pragma unroll
    for (int i = 0; i < 8; i++) {
        size_t r = (size_t)(row0 + tr * 8 + i);
#pragma unroll
        for (int j = 0; j < 8; j += 4) {
            float4 o;
            o.x = acc[i][j + 0] + bias[tc * 8 + j + 0];
            o.y = acc[i][j + 1] + bias[tc * 8 + j + 1];
            o.z = acc[i][j + 2] + bias[tc * 8 + j + 2];
            o.w = acc[i][j + 3] + bias[tc * 8 + j + 3];
            if (relu) {
                o.x = fmaxf(o.x, 0.0f); o.y = fmaxf(o.y, 0.0f);
                o.z = fmaxf(o.z, 0.0f); o.w = fmaxf(o.w, 0.0f);
            }
            *(float4*)(C + r * 128 + tc * 8 + j) = o;
        }
    }
}

// ---------------- GCN aggregation: one CTA per (graph, feature half) --------
// Builds per-dst CSR in shared, stages hs[n] = dinv[n]*h1[n] (64 feats) in
// shared, then each warp accumulates one dst node (no atomics in hot loop).
// out[d] = relu( dinv[d]*(hs[d] + sum_{in-edges} hs[src]) + b_gcn )
__global__ __launch_bounds__(1024, 1) void gcn_agg(
    const int* __restrict__ esrc, const int* __restrict__ edst,
    const float* __restrict__ b_gcn)
{
    extern __shared__ char smraw[];
    float* hs        = (float*)smraw;              // 512*64 floats (128 KB)
    int*   csr       = (int*)(hs + NPGn * 64);     // 8192 ints
    int*   row_start = csr + EPGn;                 // 513 ints
    int*   cnt       = row_start + NPGn + 1;       // 512 ints
    float* dinv      = (float*)(cnt + NPGn);       // 512 floats

    int g = blockIdx.x, hh = blockIdx.y;
    int tid = threadIdx.x;
    int ebase = g * EPGn, nbase = g * NPGn;

    if (tid < NPGn) cnt[tid] = 0;
    __syncthreads();

    // in-degree counts
    for (int e = tid; e < EPGn; e += 1024)
        atomicAdd(&cnt[edst[ebase + e] - nbase], 1);
    __syncthreads();

    // dinv (deg = count + self loop) and scan seed
    if (tid < NPGn) {
        int c = cnt[tid];
        dinv[tid] = rsqrtf((float)(c + 1));
        row_start[tid + 1] = c;
    }
    if (tid == 0) row_start[0] = 0;
    __syncthreads();

    // inclusive Hillis-Steele scan over row_start[1..512]
    for (int off = 1; off < NPGn; off <<= 1) {
        int t = 0;
        if (tid < NPGn && tid >= off) t = row_start[1 + tid - off];
        __syncthreads();
        if (tid < NPGn && tid >= off) row_start[1 + tid] += t;
        __syncthreads();
    }
    if (tid < NPGn) cnt[tid] = 0;
    __syncthreads();

    // scatter edges into CSR, and stage scaled features
    for (int e = tid; e < EPGn; e += 1024) {
        int d = edst[ebase + e] - nbase;
        int s = esrc[ebase + e] - nbase;
        int pos = row_start[d] + atomicAdd(&cnt[d], 1);
        csr[pos] = s;
    }
    for (int i = tid; i < NPGn * 16; i += 1024) {
        int n = i >> 4, q = (i & 15) << 2;
        float4 v = *(const float4*)(g_h1 + (size_t)(nbase + n) * Hn + hh * 64 + q);
        float dn = dinv[n];
        v.x *= dn; v.y *= dn; v.z *= dn; v.w *= dn;
        *(float4*)(hs + n * 64 + q) = v;
    }
    __syncthreads();

    // per-warp dst-node accumulation
    int lane = tid & 31, warp = tid >> 5;
    int f = hh * 64 + lane * 2;
    float b0 = b_gcn[f], b1 = b_gcn[f + 1];
    for (int d = warp; d < NPGn; d += 32) {
        float2 acc = *(const float2*)(hs + d * 64 + lane * 2);  // self-loop term
        int beg = row_start[d], end = row_start[d + 1];
        for (int e = beg; e < end; e++) {
            int s = csr[e];
            float2 v = *(const float2*)(hs + s * 64 + lane * 2);
            acc.x += v.x; acc.y += v.y;
        }
        float dd = dinv[d];
        float2 o;
        o.x = fmaxf(fmaf(dd, acc.x, b0), 0.0f);
        o.y = fmaxf(fmaf(dd, acc.y, b1), 0.0f);
        *(float2*)(g_h2 + (size_t)(nbase + d) * Hn + f) = o;
    }
}

// ---------------- pooling: virt[g] = ew[g]^T (64x512) @ h2[g] (512x128) -----
// One CTA per graph, 128 threads, 8x8 register tiles, BK=16.
__global__ __launch_bounds__(128) void pool_kernel(const float* __restrict__ ew)
{
    __shared__ float Ews[16][64];    // [n][v]
    __shared__ float Hs[16][128];    // [n][h]
    int g = blockIdx.x;
    int tid = threadIdx.x;
    int tr = tid >> 4;   // 0..7  -> v rows tr*8..+7
    int tc = tid & 15;   // 0..15 -> h cols tc*8..+7
    const float* ewg = ew + (size_t)g * NPGn * Vn;
    const float* hg  = g_h2 + (size_t)g * NPGn * Hn;

    float acc[8][8];
#pragma unroll
    for (int i = 0; i < 8; i++)
#pragma unroll
        for (int j = 0; j < 8; j++) acc[i][j] = 0.0f;

    for (int n0 = 0; n0 < NPGn; n0 += 16) {
        __syncthreads();
#pragma unroll
        for (int t = 0; t < 2; t++) {              // 256 float4 for Ews
            int i = t * 128 + tid;
            int n = i >> 4, v4 = (i & 15) * 4;
            *(float4*)&Ews[n][v4] = *(const float4*)(ewg + (size_t)(n0 + n) * Vn + v4);
        }
#pragma unroll
        for (int t = 0; t < 4; t++) {              // 512 float4 for Hs
            int i = t * 128 + tid;
            int n = i >> 5, h4 = (i & 31) * 4;
            *(float4*)&Hs[n][h4] = *(const float4*)(hg + (size_t)(n0 + n) * Hn + h4);
        }
        __syncthreads();
#pragma unroll
        for (int kk = 0; kk < 16; kk++) {
            float am[8], bn[8];
#pragma unroll
            for (int i = 0; i < 8; i++) am[i] = Ews[kk][tr * 8 + i];
#pragma unroll
            for (int j = 0; j < 8; j++) bn[j] = Hs[kk][tc * 8 + j];
#pragma unroll
            for (int i = 0; i < 8; i++)
#pragma unroll
                for (int j = 0; j < 8; j++)
                    acc[i][j] = fmaf(am[i], bn[j], acc[i][j]);
        }
    }

#pragma unroll
    for (int i = 0; i < 8; i++) {
        size_t r = (size_t)g * Vn + tr * 8 + i;
#pragma unroll
        for (int j = 0; j < 8; j += 4) {
            float4 o = make_float4(acc[i][j], acc[i][j + 1], acc[i][j + 2], acc[i][j + 3]);
            *(float4*)(g_virt + r * Hn + tc * 8 + j) = o;
        }
    }
}

// ---------------- mean over virtual nodes -----------------------------------
__global__ void mean_v_kernel()
{
    int idx = blockIdx.x * blockDim.x + threadIdx.x;
    if (idx >= Gn * Hn) return;
    int g = idx >> 7, h = idx & 127;
    const float* p = g_virt2 + (size_t)g * Vn * Hn + h;
    float s = 0.0f;
#pragma unroll
    for (int v = 0; v < Vn; v++) s += p[(size_t)v * Hn];
    g_m2[idx] = s * (1.0f / 64.0f);
}

// ---------------- launch ----------------------------------------------------
extern "C" void kernel_launch(void* const* d_in, const int* in_sizes, int n_in,
                              void* d_out, int out_size)
{
    const float* x     = (const float*)d_in[0];
    const int*   eidx  = (const int*)d_in[1];
    // d_in[2] = batch (unused: graphs contiguous & equal-size, as reference exploits)
    const float* W_emb = (const float*)d_in[3];
    const float* b_emb = (const float*)d_in[4];
    const float* W_gcn = (const float*)d_in[5];
    const float* b_gcn = (const float*)d_in[6];
    const float* ew    = (const float*)d_in[7];
    const float* vW1   = (const float*)d_in[8];
    const float* vb1   = (const float*)d_in[9];
    const float* vW2   = (const float*)d_in[10];
    const float* vb2   = (const float*)d_in[11];
    const float* mW1   = (const float*)d_in[12];
    const float* mb1   = (const float*)d_in[13];
    const float* mW2   = (const float*)d_in[14];
    const float* mb2   = (const float*)d_in[15];

    const int* esrc = eidx;
    const int* edst = eidx + En;

    float *p_Wf, *p_bf, *p_h1, *p_virt, *p_virt2, *p_m2, *p_gf, *p_f1;
    cudaGetSymbolAddress((void**)&p_Wf,    g_Wf);
    cudaGetSymbolAddress((void**)&p_bf,    g_bf);
    cudaGetSymbolAddress((void**)&p_h1,    g_h1);
    cudaGetSymbolAddress((void**)&p_virt,  g_virt);
    cudaGetSymbolAddress((void**)&p_virt2, g_virt2);
    cudaGetSymbolAddress((void**)&p_m2,    g_m2);
    cudaGetSymbolAddress((void**)&p_gf,    g_gf);
    cudaGetSymbolAddress((void**)&p_f1,    g_f1);

    int smbytes = (NPGn * 64) * 4 + EPGn * 4 + (NPGn + 1) * 4 + NPGn * 4 + NPGn * 4;
    cudaFuncSetAttribute(gcn_agg, cudaFuncAttributeMaxDynamicSharedMemorySize, smbytes);

    // 1) fused pre-aggregation weights: W_f = W_emb @ W_gcn, b_f = b_emb @ W_gcn
    small_gemm<<<64, 256>>>(W_emb, W_gcn, nullptr, p_Wf, 128, 128, 128, 0);
    small_gemm<<<1, 128>>>(b_emb, W_gcn, nullptr, p_bf, 1, 128, 128, 0);
    // 2) h1 = x @ W_f + b_f
    sgemm128<<<Nn / 128, 256>>>(x, p_Wf, p_bf, p_h1, 0);
    // 3) GCN aggregation + b_gcn + relu -> h2
    gcn_agg<<<dim3(Gn, 2), 1024, smbytes>>>(esrc, edst, b_gcn);
    // 4) virtual-node pooling -> virt
    pool_kernel<<<Gn, 128>>>(ew);
    // 5) virt2 = relu(virt @ vW1 + vb1)
    sgemm128<<<(Gn * Vn) / 128, 256>>>(p_virt, vW1, vb1, p_virt2, 1);
    // 6) m2 = mean_v(virt2)   (vW2 pushed past the mean)
    mean_v_kernel<<<64, 256>>>();
    // 7) gf = m2 @ vW2 + vb2 ; f1 = relu(gf @ mW1 + mb1) ; out = f1 @ mW2 + mb2
    small_gemm<<<64, 256>>>(p_m2, vW2, vb2, p_gf, 128, 128, 128, 0);
    small_gemm<<<64, 256>>>(p_gf, mW1, mb1, p_f1, 128, 128, 128, 1);
    small_gemm<<<5, 256>>>(p_f1, mW2, mb2, (float*)d_out, 128, OUTn, 128, 0);
}

// round 2
// speedup vs baseline: 1.2461x; 1.2461x over previous
#include <cuda_runtime.h>
#include <mma.h>
using namespace nvcuda;

// Problem constants
#define Gn    128
#define NPGn  512
#define Hn    128
#define Vn    64
#define EPGn  8192
#define Nn    (Gn * NPGn)      // 65536
#define En    (Gn * EPGn)      // 1048576
#define OUTn  10

// ---------------- scratch (device globals; no allocation allowed) -----------
__device__ float g_Wf[Hn * Hn];
__device__ float g_bf[Hn];
__device__ float g_h1[(size_t)Nn * Hn];          // 32 MB
__device__ float g_h2[(size_t)Nn * Hn];          // 32 MB
__device__ float g_virt[(size_t)Gn * Vn * Hn];   // 4 MB
__device__ float g_virt2[(size_t)Gn * Vn * Hn];  // 4 MB
__device__ float g_m2[Gn * Hn];
__device__ float g_gf[Gn * Hn];
__device__ float g_f1[Gn * Hn];

// ---------------- tiny generic GEMM: one thread per output ------------------
__global__ void small_gemm(const float* __restrict__ A, const float* __restrict__ B,
                           const float* __restrict__ bias, float* __restrict__ C,
                           int M, int N, int K, int relu)
{
    int idx = blockIdx.x * blockDim.x + threadIdx.x;
    if (idx >= M * N) return;
    int m = idx / N, n = idx - m * N;
    float acc = bias ? bias[n] : 0.0f;
    for (int k = 0; k < K; k++)
        acc = fmaf(A[(size_t)m * K + k], B[(size_t)k * N + n], acc);
    if (relu) acc = fmaxf(acc, 0.0f);
    C[idx] = acc;
}

// fused W_f = W_emb @ W_gcn and b_f = b_emb @ W_gcn
__global__ void prep_wf(const float* __restrict__ W_emb, const float* __restrict__ b_emb,
                        const float* __restrict__ W_gcn)
{
    int idx = blockIdx.x * blockDim.x + threadIdx.x;
    if (idx >= 129 * 128) return;
    int m = idx >> 7, n = idx & 127;
    float acc = 0.0f;
    if (m < 128) {
        for (int k = 0; k < 128; k++)
            acc = fmaf(W_emb[m * 128 + k], W_gcn[k * 128 + n], acc);
        g_Wf[m * 128 + n] = acc;
    } else {
        for (int k = 0; k < 128; k++)
            acc = fmaf(b_emb[k], W_gcn[k * 128 + n], acc);
        g_bf[n] = acc;
    }
}

// ---------------- tf32 tensor-core GEMM: C[M,128]=A[M,128]@B[128,128]+bias --
// 128x128 block tile, 8 warps; warp (wm 0..3, wn 0..1) owns 32x64.
__global__ __launch_bounds__(256) void sgemm_tc(
    const float* __restrict__ A, const float* __restrict__ B,
    const float* __restrict__ bias, float* __restrict__ C, int relu)
{
    __shared__ float As[128][36];
    __shared__ float Bs[32][132];
    __shared__ float biasRep[16][132];

    int tid = threadIdx.x;
    int warp = tid >> 5;
    int wm = warp >> 1, wn = warp & 1;
    size_t row0 = (size_t)blockIdx.x * 128;

    for (int i = tid; i < 16 * 128; i += 256) {
        int r = i >> 7, c = i & 127;
        biasRep[r][c] = bias[c];
    }
    __syncthreads();

    wmma::fragment<wmma::accumulator, 16, 16, 8, float> acc[2][4];
#pragma unroll
    for (int m = 0; m < 2; m++)
#pragma unroll
        for (int n = 0; n < 4; n++)
            wmma::load_matrix_sync(acc[m][n], &biasRep[0][wn * 64 + n * 16], 132,
                                   wmma::mem_row_major);

    for (int k0 = 0; k0 < 128; k0 += 32) {
        __syncthreads();
#pragma unroll
        for (int i = tid; i < 1024; i += 256) {
            int r = i >> 3, c = (i & 7) * 4;
            *(float4*)&As[r][c] = *(const float4*)(A + (row0 + r) * 128 + k0 + c);
        }
#pragma unroll
        for (int i = tid; i < 1024; i += 256) {
            int r = i >> 5, c = (i & 31) * 4;
            *(float4*)&Bs[r][c] = *(const float4*)(B + (size_t)(k0 + r) * 128 + c);
        }
        __syncthreads();
#pragma unroll
        for (int kk = 0; kk < 32; kk += 8) {
            wmma::fragment<wmma::matrix_a, 16, 16, 8, wmma::precision::tf32,
                           wmma::row_major> af[2];
            wmma::fragment<wmma::matrix_b, 16, 16, 8, wmma::precision::tf32,
                           wmma::row_major> bf[4];
#pragma unroll
            for (int m = 0; m < 2; m++) {
                wmma::load_matrix_sync(af[m], &As[wm * 32 + m * 16][kk], 36);
#pragma unroll
                for (int t = 0; t < af[m].num_elements; t++)
                    af[m].x[t] = wmma::__float_to_tf32(af[m].x[t]);
            }
#pragma unroll
            for (int n = 0; n < 4; n++) {
                wmma::load_matrix_sync(bf[n], &Bs[kk][wn * 64 + n * 16], 132);
#pragma unroll
                for (int t = 0; t < bf[n].num_elements; t++)
                    bf[n].x[t] = wmma::__float_to_tf32(bf[n].x[t]);
            }
#pragma unroll
            for (int m = 0; m < 2; m++)
#pragma unroll
                for (int n = 0; n < 4; n++)
                    wmma::mma_sync(acc[m][n], af[m], bf[n], acc[m][n]);
        }
    }

#pragma unroll
    for (int m = 0; m < 2; m++)
#pragma unroll
        for (int n = 0; n < 4; n++) {
            if (relu) {
#pragma unroll
                for (int t = 0; t < acc[m][n].num_elements; t++)
                    acc[m][n].x[t] = fmaxf(acc[m][n].x[t], 0.0f);
            }
            wmma::store_matrix_sync(C + (row0 + wm * 32 + m * 16) * 128 + wn * 64 + n * 16,
                                    acc[m][n], 128, wmma::mem_row_major);
        }
}

// ---------------- GCN aggregation: one CTA per graph, CSR built once --------
__global__ __launch_bounds__(1024, 1) void gcn_agg(
    const int* __restrict__ esrc, const int* __restrict__ edst,
    const float* __restrict__ b_gcn)
{
    extern __shared__ char smraw[];
    float* hs        = (float*)smraw;              // 512*64 floats (128 KB)
    int*   csr       = (int*)(hs + NPGn * 64);     // 8192 ints
    int*   row_start = csr + EPGn;                 // 513 ints
    int*   cnt       = row_start + NPGn + 1;       // 512 ints
    float* dinv      = (float*)(cnt + NPGn);       // 512 floats

    int g = blockIdx.x;
    int tid = threadIdx.x;
    int ebase = g * EPGn, nbase = g * NPGn;

    if (tid < NPGn) cnt[tid] = 0;
    __syncthreads();

    for (int e = tid; e < EPGn; e += 1024)
        atomicAdd(&cnt[edst[ebase + e] - nbase], 1);
    __syncthreads();

    if (tid < NPGn) {
        int c = cnt[tid];
        dinv[tid] = rsqrtf((float)(c + 1));
        row_start[tid + 1] = c;
    }
    if (tid == 0) row_start[0] = 0;
    __syncthreads();

    for (int off = 1; off < NPGn; off <<= 1) {
        int t = 0;
        if (tid < NPGn && tid >= off) t = row_start[1 + tid - off];
        __syncthreads();
        if (tid < NPGn && tid >= off) row_start[1 + tid] += t;
        __syncthreads();
    }
    if (tid < NPGn) cnt[tid] = 0;
    __syncthreads();

    for (int e = tid; e < EPGn; e += 1024) {
        int d = edst[ebase + e] - nbase;
        int s = esrc[ebase + e] - nbase;
        int pos = row_start[d] + atomicAdd(&cnt[d], 1);
        csr[pos] = s;
    }

    int lane = tid & 31, warp = tid >> 5;

    for (int hh = 0; hh < 2; hh++) {
        __syncthreads();   // protect hs (prev pass readers) & csr (first pass)
        for (int i = tid; i < NPGn * 16; i += 1024) {
            int n = i >> 4, q = (i & 15) << 2;
            float4 v = *(const float4*)(g_h1 + (size_t)(nbase + n) * Hn + hh * 64 + q);
            float dn = dinv[n];
            v.x *= dn; v.y *= dn; v.z *= dn; v.w *= dn;
            *(float4*)(hs + n * 64 + q) = v;
        }
        __syncthreads();

        int f = hh * 64 + lane * 2;
        float b0 = b_gcn[f], b1 = b_gcn[f + 1];
        for (int d = warp; d < NPGn; d += 32) {
            float2 acc = *(const float2*)(hs + d * 64 + lane * 2);  // self loop
            float2 a1 = {0.f, 0.f}, a2 = {0.f, 0.f}, a3 = {0.f, 0.f};
            int e = row_start[d], end = row_start[d + 1];
            for (; e + 4 <= end; e += 4) {
                int s0 = csr[e], s1 = csr[e + 1], s2 = csr[e + 2], s3 = csr[e + 3];
                float2 v0 = *(const float2*)(hs + s0 * 64 + lane * 2);
                float2 v1 = *(const float2*)(hs + s1 * 64 + lane * 2);
                float2 v2 = *(const float2*)(hs + s2 * 64 + lane * 2);
                float2 v3 = *(const float2*)(hs + s3 * 64 + lane * 2);
                acc.x += v0.x; acc.y += v0.y;
                a1.x += v1.x;  a1.y += v1.y;
                a2.x += v2.x;  a2.y += v2.y;
                a3.x += v3.x;  a3.y += v3.y;
            }
            for (; e < end; e++) {
                int s = csr[e];
                float2 v = *(const float2*)(hs + s * 64 + lane * 2);
                acc.x += v.x; acc.y += v.y;
            }
            acc.x += a1.x + a2.x + a3.x;
            acc.y += a1.y + a2.y + a3.y;
            float dd = dinv[d];
            float2 o;
            o.x = fmaxf(fmaf(dd, acc.x, b0), 0.0f);
            o.y = fmaxf(fmaf(dd, acc.y, b1), 0.0f);
            *(float2*)(g_h2 + (size_t)(nbase + d) * Hn + f) = o;
        }
    }
}

// ---------------- pooling (tensor cores): virt[g]=ew[g]^T(64x512)@h2[g] -----
// One CTA per graph, 8 warps; warp (wm 0..3, wn 0..1) owns 16x64.
__global__ __launch_bounds__(256) void pool_tc(const float* __restrict__ ew)
{
    __shared__ float Es[32][68];    // [k][v]  (col-major A view, ld=68)
    __shared__ float Hs[32][132];   // [k][h]

    int tid = threadIdx.x;
    int warp = tid >> 5;
    int wm = warp >> 1, wn = warp & 1;
    int g = blockIdx.x;
    const float* ewg = ew + (size_t)g * NPGn * Vn;
    const float* hg  = g_h2 + (size_t)g * NPGn * Hn;

    wmma::fragment<wmma::accumulator, 16, 16, 8, float> acc[4];
#pragma unroll
    for (int n = 0; n < 4; n++) wmma::fill_fragment(acc[n], 0.0f);

    for (int n0 = 0; n0 < NPGn; n0 += 32) {
        __syncthreads();
#pragma unroll
        for (int i = tid; i < 32 * 16; i += 256) {
            int k = i >> 4, c = (i & 15) * 4;
            *(float4*)&Es[k][c] = *(const float4*)(ewg + (size_t)(n0 + k) * Vn + c);
        }
#pragma unroll
        for (int i = tid; i < 32 * 32; i += 256) {
            int k = i >> 5, c = (i & 31) * 4;
            *(float4*)&Hs[k][c] = *(const float4*)(hg + (size_t)(n0 + k) * Hn + c);
        }
        __syncthreads();
#pragma unroll
        for (int kk = 0; kk < 32; kk += 8) {
            wmma::fragment<wmma::matrix_a, 16, 16, 8, wmma::precision::tf32,
                           wmma::col_major> af;
            wmma::load_matrix_sync(af, &Es[kk][wm * 16], 68);
#pragma unroll
            for (int t = 0; t < af.num_elements; t++)
                af.x[t] = wmma::__float_to_tf32(af.x[t]);
            wmma::fragment<wmma::matrix_b, 16, 16, 8, wmma::precision::tf32,
                           wmma::row_major> bf[4];
#pragma unroll
            for (int n = 0; n < 4; n++) {
                wmma::load_matrix_sync(bf[n], &Hs[kk][wn * 64 + n * 16], 132);
#pragma unroll
                for (int t = 0; t < bf[n].num_elements; t++)
                    bf[n].x[t] = wmma::__float_to_tf32(bf[n].x[t]);
            }
#pragma unroll
            for (int n = 0; n < 4; n++)
                wmma::mma_sync(acc[n], af, bf[n], acc[n]);
        }
    }

#pragma unroll
    for (int n = 0; n < 4; n++)
        wmma::store_matrix_sync(g_virt + ((size_t)g * Vn + wm * 16) * Hn + wn * 64 + n * 16,
                                acc[n], 128, wmma::mem_row_major);
}

// ---------------- mean over virtual nodes -----------------------------------
__global__ void mean_v_kernel()
{
    int idx = blockIdx.x * blockDim.x + threadIdx.x;
    if (idx >= Gn * Hn) return;
    int g = idx >> 7, h = idx & 127;
    const float* p = g_virt2 + (size_t)g * Vn * Hn + h;
    float s = 0.0f;
#pragma unroll
    for (int v = 0; v < Vn; v++) s += p[(size_t)v * Hn];
    g_m2[idx] = s * (1.0f / 64.0f);
}

// ---------------- launch ----------------------------------------------------
extern "C" void kernel_launch(void* const* d_in, const int* in_sizes, int n_in,
                              void* d_out, int out_size)
{
    const float* x     = (const float*)d_in[0];
    const int*   eidx  = (const int*)d_in[1];
    // d_in[2] = batch (unused: graphs contiguous & equal-size)
    const float* W_emb = (const float*)d_in[3];
    const float* b_emb = (const float*)d_in[4];
    const float* W_gcn = (const float*)d_in[5];
    const float* b_gcn = (const float*)d_in[6];
    const float* ew    = (const float*)d_in[7];
    const float* vW1   = (const float*)d_in[8];
    const float* vb1   = (const float*)d_in[9];
    const float* vW2   = (const float*)d_in[10];
    const float* vb2   = (const float*)d_in[11];
    const float* mW1   = (const float*)d_in[12];
    const float* mb1   = (const float*)d_in[13];
    const float* mW2   = (const float*)d_in[14];
    const float* mb2   = (const float*)d_in[15];

    const int* esrc = eidx;
    const int* edst = eidx + En;

    float *p_Wf, *p_bf, *p_h1, *p_virt, *p_virt2, *p_m2, *p_gf, *p_f1;
    cudaGetSymbolAddress((void**)&p_Wf,    g_Wf);
    cudaGetSymbolAddress((void**)&p_bf,    g_bf);
    cudaGetSymbolAddress((void**)&p_h1,    g_h1);
    cudaGetSymbolAddress((void**)&p_virt,  g_virt);
    cudaGetSymbolAddress((void**)&p_virt2, g_virt2);
    cudaGetSymbolAddress((void**)&p_m2,    g_m2);
    cudaGetSymbolAddress((void**)&p_gf,    g_gf);
    cudaGetSymbolAddress((void**)&p_f1,    g_f1);

    int smbytes = (NPGn * 64) * 4 + EPGn * 4 + (NPGn + 1) * 4 + NPGn * 4 + NPGn * 4;
    cudaFuncSetAttribute(gcn_agg, cudaFuncAttributeMaxDynamicSharedMemorySize, smbytes);

    // 1) fused pre-aggregation weights (W_f, b_f)
    prep_wf<<<(129 * 128 + 255) / 256, 256>>>(W_emb, b_emb, W_gcn);
    // 2) h1 = x @ W_f + b_f                 (tf32 tensor cores)
    sgemm_tc<<<Nn / 128, 256>>>(x, p_Wf, p_bf, p_h1, 0);
    // 3) GCN aggregation + b_gcn + relu -> h2
    gcn_agg<<<Gn, 1024, smbytes>>>(esrc, edst, b_gcn);
    // 4) virtual-node pooling -> virt       (tf32 tensor cores)
    pool_tc<<<Gn, 256>>>(ew);
    // 5) virt2 = relu(virt @ vW1 + vb1)     (tf32 tensor cores)
    sgemm_tc<<<(Gn * Vn) / 128, 256>>>(p_virt, vW1, vb1, p_virt2, 1);
    // 6) m2 = mean_v(virt2)    (vW2 pushed past the mean)
    mean_v_kernel<<<64, 256>>>();
    // 7) tail: gf = m2 @ vW2 + vb2; f1 = relu(gf @ mW1 + mb1); out = f1 @ mW2 + mb2
    small_gemm<<<64, 256>>>(p_m2, vW2, vb2, p_gf, 128, 128, 128, 0);
    small_gemm<<<64, 256>>>(p_gf, mW1, mb1, p_f1, 128, 128, 128, 1);
    small_gemm<<<5, 256>>>(p_f1, mW2, mb2, (float*)d_out, 128, OUTn, 128, 0);
}

// round 4
// speedup vs baseline: 1.4221x; 1.1413x over previous
#include <cuda_runtime.h>
#include <mma.h>
using namespace nvcuda;

// Problem constants
#define Gn    128
#define NPGn  512
#define Hn    128
#define Vn    64
#define EPGn  8192
#define Nn    (Gn * NPGn)      // 65536
#define En    (Gn * EPGn)      // 1048576
#define OUTn  10
#define PSLICES 4

// ---------------- scratch (device globals; no allocation allowed) -----------
__device__ float g_Wf[Hn * Hn];
__device__ float g_bf[Hn];
__device__ float g_h1[(size_t)Nn * Hn];          // 32 MB
__device__ float g_h2[(size_t)Nn * Hn];          // 32 MB
__device__ float g_poolPart[PSLICES][(size_t)Gn * Vn * Hn]; // 16 MB
__device__ float g_virt[(size_t)Gn * Vn * Hn];   // 4 MB
__device__ float g_virt2[(size_t)Gn * Vn * Hn];  // 4 MB

// ---------------- prep: W_f = W_emb @ W_gcn, b_f = b_emb @ W_gcn ------------
__global__ __launch_bounds__(128) void prep_wf(
    const float* __restrict__ W_emb, const float* __restrict__ b_emb,
    const float* __restrict__ W_gcn)
{
    __shared__ float arow[128];
    int m = blockIdx.x;            // 0..128 (128 == bias row)
    int n = threadIdx.x;
    const float* src = (m < 128) ? (W_emb + m * 128) : b_emb;
    arow[n] = src[n];
    __syncthreads();
    float acc = 0.0f;
#pragma unroll 8
    for (int k = 0; k < 128; k++)
        acc = fmaf(arow[k], W_gcn[k * 128 + n], acc);
    if (m < 128) g_Wf[m * 128 + n] = acc;
    else         g_bf[n] = acc;
}

// ---------------- cp.async helpers ------------------------------------------
__device__ __forceinline__ void cp_async16(void* smem_dst, const void* gmem_src) {
    unsigned saddr = (unsigned)__cvta_generic_to_shared(smem_dst);
    asm volatile("cp.async.ca.shared.global [%0], [%1], 16;\n"
                 :: "r"(saddr), "l"(gmem_src));
}
__device__ __forceinline__ void cp_async_commit() {
    asm volatile("cp.async.commit_group;\n");
}
template <int N>
__device__ __forceinline__ void cp_async_wait() {
    asm volatile("cp.async.wait_group %0;\n" :: "n"(N));
}

// ---------------- tf32 tensor-core GEMM: C[M,128]=A[M,128]@B[128,128]+bias --
// 128x128 block tile, 8 warps, 2-stage cp.async pipeline over 4 K-chunks.
// Shared tiles live in DYNAMIC shared memory (79,104 B; above static limit).
#define SG_AS(st)      (sm_dyn + (st) * 128 * 36)                   // [128][36]
#define SG_BS(st)      (sm_dyn + 2 * 128 * 36 + (st) * 32 * 132)    // [32][132]
#define SG_BIAS        (sm_dyn + 2 * 128 * 36 + 2 * 32 * 132)       // [16][132]
#define SGEMM_SMEM     ((2 * 128 * 36 + 2 * 32 * 132 + 16 * 132) * 4)

__global__ __launch_bounds__(256) void sgemm_tc(
    const float* __restrict__ A, const float* __restrict__ B,
    const float* __restrict__ bias, float* __restrict__ C, int relu)
{
    extern __shared__ float sm_dyn[];

    int tid = threadIdx.x;
    int warp = tid >> 5;
    int wm = warp >> 1, wn = warp & 1;
    size_t row0 = (size_t)blockIdx.x * 128;

    float* biasRep = SG_BIAS;
    for (int i = tid; i < 16 * 128; i += 256) {
        int r = i >> 7, c = i & 127;
        biasRep[r * 132 + c] = bias[c];
    }

    auto issue_chunk = [&](int k0, int st) {
        float* as = SG_AS(st);
        float* bs = SG_BS(st);
#pragma unroll
        for (int i = tid; i < 1024; i += 256) {
            int r = i >> 3, c = (i & 7) * 4;
            cp_async16(as + r * 36 + c, A + (row0 + r) * 128 + k0 + c);
        }
#pragma unroll
        for (int i = tid; i < 1024; i += 256) {
            int r = i >> 5, c = (i & 31) * 4;
            cp_async16(bs + r * 132 + c, B + (size_t)(k0 + r) * 128 + c);
        }
        cp_async_commit();
    };

    issue_chunk(0, 0);
    issue_chunk(32, 1);

    __syncthreads();  // biasRep ready
    wmma::fragment<wmma::accumulator, 16, 16, 8, float> acc[2][4];
#pragma unroll
    for (int m = 0; m < 2; m++)
#pragma unroll
        for (int n = 0; n < 4; n++)
            wmma::load_matrix_sync(acc[m][n], biasRep + wn * 64 + n * 16, 132,
                                   wmma::mem_row_major);

#pragma unroll
    for (int it = 0; it < 4; it++) {
        int st = it & 1;
        float* as = SG_AS(st);
        float* bs = SG_BS(st);
        if (it < 3) cp_async_wait<1>(); else cp_async_wait<0>();
        __syncthreads();
#pragma unroll
        for (int kk = 0; kk < 32; kk += 8) {
            wmma::fragment<wmma::matrix_a, 16, 16, 8, wmma::precision::tf32,
                           wmma::row_major> af[2];
            wmma::fragment<wmma::matrix_b, 16, 16, 8, wmma::precision::tf32,
                           wmma::row_major> bf[4];
#pragma unroll
            for (int m = 0; m < 2; m++) {
                wmma::load_matrix_sync(af[m], as + (wm * 32 + m * 16) * 36 + kk, 36);
#pragma unroll
                for (int t = 0; t < af[m].num_elements; t++)
                    af[m].x[t] = wmma::__float_to_tf32(af[m].x[t]);
            }
#pragma unroll
            for (int n = 0; n < 4; n++) {
                wmma::load_matrix_sync(bf[n], bs + kk * 132 + wn * 64 + n * 16, 132);
#pragma unroll
                for (int t = 0; t < bf[n].num_elements; t++)
                    bf[n].x[t] = wmma::__float_to_tf32(bf[n].x[t]);
            }
#pragma unroll
            for (int m = 0; m < 2; m++)
#pragma unroll
                for (int n = 0; n < 4; n++)
                    wmma::mma_sync(acc[m][n], af[m], bf[n], acc[m][n]);
        }
        __syncthreads();
        if (it + 2 < 4) issue_chunk((it + 2) * 32, st);
    }

#pragma unroll
    for (int m = 0; m < 2; m++)
#pragma unroll
        for (int n = 0; n < 4; n++) {
            if (relu) {
#pragma unroll
                for (int t = 0; t < acc[m][n].num_elements; t++)
                    acc[m][n].x[t] = fmaxf(acc[m][n].x[t], 0.0f);
            }
            wmma::store_matrix_sync(C + (row0 + wm * 32 + m * 16) * 128 + wn * 64 + n * 16,
                                    acc[m][n], 128, wmma::mem_row_major);
        }
}

// ---------------- GCN aggregation: one CTA per graph, CSR built once --------
__global__ __launch_bounds__(1024, 1) void gcn_agg(
    const int* __restrict__ esrc, const int* __restrict__ edst,
    const float* __restrict__ b_gcn)
{
    extern __shared__ char smraw[];
    float* hs        = (float*)smraw;              // 512*64 floats (128 KB)
    int*   csr       = (int*)(hs + NPGn * 64);     // 8192 ints
    int*   row_start = csr + EPGn;                 // 513 ints
    int*   cnt       = row_start + NPGn + 1;       // 512 ints
    float* dinv      = (float*)(cnt + NPGn);       // 512 floats

    int g = blockIdx.x;
    int tid = threadIdx.x;
    int ebase = g * EPGn, nbase = g * NPGn;

    if (tid < NPGn) cnt[tid] = 0;
    __syncthreads();

    for (int e = tid; e < EPGn; e += 1024)
        atomicAdd(&cnt[edst[ebase + e] - nbase], 1);
    __syncthreads();

    if (tid < NPGn) {
        int c = cnt[tid];
        dinv[tid] = rsqrtf((float)(c + 1));
        row_start[tid + 1] = c;
    }
    if (tid == 0) row_start[0] = 0;
    __syncthreads();

    for (int off = 1; off < NPGn; off <<= 1) {
        int t = 0;
        if (tid < NPGn && tid >= off) t = row_start[1 + tid - off];
        __syncthreads();
        if (tid < NPGn && tid >= off) row_start[1 + tid] += t;
        __syncthreads();
    }
    if (tid < NPGn) cnt[tid] = 0;
    __syncthreads();

    for (int e = tid; e < EPGn; e += 1024) {
        int d = edst[ebase + e] - nbase;
        int s = esrc[ebase + e] - nbase;
        int pos = row_start[d] + atomicAdd(&cnt[d], 1);
        csr[pos] = s;
    }

    int lane = tid & 31, warp = tid >> 5;

    for (int hh = 0; hh < 2; hh++) {
        __syncthreads();
        for (int i = tid; i < NPGn * 16; i += 1024) {
            int n = i >> 4, q = (i & 15) << 2;
            float4 v = *(const float4*)(g_h1 + (size_t)(nbase + n) * Hn + hh * 64 + q);
            float dn = dinv[n];
            v.x *= dn; v.y *= dn; v.z *= dn; v.w *= dn;
            *(float4*)(hs + n * 64 + q) = v;
        }
        __syncthreads();

        int f = hh * 64 + lane * 2;
        float b0 = b_gcn[f], b1 = b_gcn[f + 1];
        for (int d = warp; d < NPGn; d += 32) {
            float2 acc = *(const float2*)(hs + d * 64 + lane * 2);  // self loop
            float2 a1 = {0.f, 0.f}, a2 = {0.f, 0.f}, a3 = {0.f, 0.f};
            int e = row_start[d], end = row_start[d + 1];
            for (; e + 4 <= end; e += 4) {
                int s0 = csr[e], s1 = csr[e + 1], s2 = csr[e + 2], s3 = csr[e + 3];
                float2 v0 = *(const float2*)(hs + s0 * 64 + lane * 2);
                float2 v1 = *(const float2*)(hs + s1 * 64 + lane * 2);
                float2 v2 = *(const float2*)(hs + s2 * 64 + lane * 2);
                float2 v3 = *(const float2*)(hs + s3 * 64 + lane * 2);
                acc.x += v0.x; acc.y += v0.y;
                a1.x += v1.x;  a1.y += v1.y;
                a2.x += v2.x;  a2.y += v2.y;
                a3.x += v3.x;  a3.y += v3.y;
            }
            for (; e < end; e++) {
                int s = csr[e];
                float2 v = *(const float2*)(hs + s * 64 + lane * 2);
                acc.x += v.x; acc.y += v.y;
            }
            acc.x += a1.x + a2.x + a3.x;
            acc.y += a1.y + a2.y + a3.y;
            float dd = dinv[d];
            float2 o;
            o.x = fmaxf(fmaf(dd, acc.x, b0), 0.0f);
            o.y = fmaxf(fmaf(dd, acc.y, b1), 0.0f);
            *(float2*)(g_h2 + (size_t)(nbase + d) * Hn + f) = o;
        }
    }
}

// ---------------- pooling (tf32, split-K): partial over 128 nodes -----------
__global__ __launch_bounds__(256) void pool_tc(const float* __restrict__ ew)
{
    __shared__ float Es[32][68];    // [k][v]
    __shared__ float Hs[32][132];   // [k][h]

    int tid = threadIdx.x;
    int warp = tid >> 5;
    int wm = warp >> 1, wn = warp & 1;
    int g = blockIdx.x, sl = blockIdx.y;
    int nbeg = sl * (NPGn / PSLICES);
    const float* ewg = ew + ((size_t)g * NPGn + nbeg) * Vn;
    const float* hg  = g_h2 + ((size_t)g * NPGn + nbeg) * Hn;

    wmma::fragment<wmma::accumulator, 16, 16, 8, float> acc[4];
#pragma unroll
    for (int n = 0; n < 4; n++) wmma::fill_fragment(acc[n], 0.0f);

    for (int n0 = 0; n0 < NPGn / PSLICES; n0 += 32) {
        __syncthreads();
#pragma unroll
        for (int i = tid; i < 32 * 16; i += 256) {
            int k = i >> 4, c = (i & 15) * 4;
            *(float4*)&Es[k][c] = *(const float4*)(ewg + (size_t)(n0 + k) * Vn + c);
        }
#pragma unroll
        for (int i = tid; i < 32 * 32; i += 256) {
            int k = i >> 5, c = (i & 31) * 4;
            *(float4*)&Hs[k][c] = *(const float4*)(hg + (size_t)(n0 + k) * Hn + c);
        }
        __syncthreads();
#pragma unroll
        for (int kk = 0; kk < 32; kk += 8) {
            wmma::fragment<wmma::matrix_a, 16, 16, 8, wmma::precision::tf32,
                           wmma::col_major> af;
            wmma::load_matrix_sync(af, &Es[kk][wm * 16], 68);
#pragma unroll
            for (int t = 0; t < af.num_elements; t++)
                af.x[t] = wmma::__float_to_tf32(af.x[t]);
            wmma::fragment<wmma::matrix_b, 16, 16, 8, wmma::precision::tf32,
                           wmma::row_major> bf[4];
#pragma unroll
            for (int n = 0; n < 4; n++) {
                wmma::load_matrix_sync(bf[n], &Hs[kk][wn * 64 + n * 16], 132);
#pragma unroll
                for (int t = 0; t < bf[n].num_elements; t++)
                    bf[n].x[t] = wmma::__float_to_tf32(bf[n].x[t]);
            }
#pragma unroll
            for (int n = 0; n < 4; n++)
                wmma::mma_sync(acc[n], af, bf[n], acc[n]);
        }
    }

#pragma unroll
    for (int n = 0; n < 4; n++)
        wmma::store_matrix_sync(
            g_poolPart[sl] + ((size_t)g * Vn + wm * 16) * Hn + wn * 64 + n * 16,
            acc[n], 128, wmma::mem_row_major);
}

// ---------------- reduce split-K partials -> g_virt (float4) ----------------
__global__ void reduce_virt()
{
    int idx = blockIdx.x * blockDim.x + threadIdx.x;   // float4 index
    if (idx >= (Gn * Vn * Hn) / 4) return;
    const float4* p0 = (const float4*)g_poolPart[0];
    const float4* p1 = (const float4*)g_poolPart[1];
    const float4* p2 = (const float4*)g_poolPart[2];
    const float4* p3 = (const float4*)g_poolPart[3];
    float4 a = p0[idx], b = p1[idx], c = p2[idx], d = p3[idx];
    float4 o;
    o.x = (a.x + b.x) + (c.x + d.x);
    o.y = (a.y + b.y) + (c.y + d.y);
    o.z = (a.z + b.z) + (c.z + d.z);
    o.w = (a.w + b.w) + (c.w + d.w);
    ((float4*)g_virt)[idx] = o;
}

// ---------------- fused tail: mean_v + 3 chained GEMVs per graph ------------
__global__ __launch_bounds__(128) void tail_kernel(
    const float* __restrict__ vW2, const float* __restrict__ vb2,
    const float* __restrict__ mW1, const float* __restrict__ mb1,
    const float* __restrict__ mW2, const float* __restrict__ mb2,
    float* __restrict__ out)
{
    __shared__ float m2s[128], gfs[128], f1s[128];
    int g = blockIdx.x;
    int n = threadIdx.x;

    const float* vp = g_virt2 + (size_t)g * Vn * Hn + n;
    float s = 0.0f;
#pragma unroll 16
    for (int v = 0; v < Vn; v++) s += vp[(size_t)v * Hn];
    m2s[n] = s * (1.0f / 64.0f);
    __syncthreads();

    float acc = vb2[n];
#pragma unroll 8
    for (int k = 0; k < 128; k++) acc = fmaf(m2s[k], vW2[k * 128 + n], acc);
    gfs[n] = acc;
    __syncthreads();

    acc = mb1[n];
#pragma unroll 8
    for (int k = 0; k < 128; k++) acc = fmaf(gfs[k], mW1[k * 128 + n], acc);
    f1s[n] = fmaxf(acc, 0.0f);
    __syncthreads();

    if (n < OUTn) {
        acc = mb2[n];
#pragma unroll 8
        for (int k = 0; k < 128; k++) acc = fmaf(f1s[k], mW2[k * OUTn + n], acc);
        out[g * OUTn + n] = acc;
    }
}

// ---------------- launch ----------------------------------------------------
extern "C" void kernel_launch(void* const* d_in, const int* in_sizes, int n_in,
                              void* d_out, int out_size)
{
    const float* x     = (const float*)d_in[0];
    const int*   eidx  = (const int*)d_in[1];
    // d_in[2] = batch (unused: graphs contiguous & equal-size)
    const float* W_emb = (const float*)d_in[3];
    const float* b_emb = (const float*)d_in[4];
    const float* W_gcn = (const float*)d_in[5];
    const float* b_gcn = (const float*)d_in[6];
    const float* ew    = (const float*)d_in[7];
    const float* vW1   = (const float*)d_in[8];
    const float* vb1   = (const float*)d_in[9];
    const float* vW2   = (const float*)d_in[10];
    const float* vb2   = (const float*)d_in[11];
    const float* mW1   = (const float*)d_in[12];
    const float* mb1   = (const float*)d_in[13];
    const float* mW2   = (const float*)d_in[14];
    const float* mb2   = (const float*)d_in[15];

    const int* esrc = eidx;
    const int* edst = eidx + En;

    float *p_Wf, *p_bf, *p_h1, *p_virt, *p_virt2;
    cudaGetSymbolAddress((void**)&p_Wf,    g_Wf);
    cudaGetSymbolAddress((void**)&p_bf,    g_bf);
    cudaGetSymbolAddress((void**)&p_h1,    g_h1);
    cudaGetSymbolAddress((void**)&p_virt,  g_virt);
    cudaGetSymbolAddress((void**)&p_virt2, g_virt2);

    int smbytes = (NPGn * 64) * 4 + EPGn * 4 + (NPGn + 1) * 4 + NPGn * 4 + NPGn * 4;
    cudaFuncSetAttribute(gcn_agg, cudaFuncAttributeMaxDynamicSharedMemorySize, smbytes);
    cudaFuncSetAttribute(sgemm_tc, cudaFuncAttributeMaxDynamicSharedMemorySize, SGEMM_SMEM);

    // 1) fused pre-aggregation weights (W_f, b_f)
    prep_wf<<<129, 128>>>(W_emb, b_emb, W_gcn);
    // 2) h1 = x @ W_f + b_f                 (tf32 TC, cp.async pipeline)
    sgemm_tc<<<Nn / 128, 256, SGEMM_SMEM>>>(x, p_Wf, p_bf, p_h1, 0);
    // 3) GCN aggregation + b_gcn + relu -> h2
    gcn_agg<<<Gn, 1024, smbytes>>>(esrc, edst, b_gcn);
    // 4) virtual-node pooling, split-K x4 -> partials, then reduce -> virt
    pool_tc<<<dim3(Gn, PSLICES), 256>>>(ew);
    reduce_virt<<<(Gn * Vn * Hn / 4 + 255) / 256, 256>>>();
    // 5) virt2 = relu(virt @ vW1 + vb1)     (tf32 TC)
    sgemm_tc<<<(Gn * Vn) / 128, 256, SGEMM_SMEM>>>(p_virt, vW1, vb1, p_virt2, 1);
    // 6) fused tail: mean + 3 GEMVs -> out
    tail_kernel<<<Gn, 128>>>(vW2, vb2, mW1, mb1, mW2, mb2, (float*)d_out);
}